// round 8
// baseline (speedup 1.0000x reference)
#include <cuda_runtime.h>
#include <cuda_bf16.h>

// Output[b,s,:] == mean(knowledge, axis=0) for every (b,s):
// top_k with max_chunks == K selects a permutation of ALL knowledge rows,
// so mean(take(knowledge, top_k), axis=1) == mean(knowledge, axis=0).
//
// R7: total now tracks kernel time (6.62us == profiled). Kernel is
// latency/ramp bound, not throughput bound. This round tiles the grid in
// BOTH rows and columns: 128 CTAs = 4 col-blocks x 32 row-blocks. Each CTA
// reads only its 32KB column slice of knowledge (4 loads/thread, was 16;
// 4MB chip-wide, was 16MB), tree-reduces 16 partials in smem, and writes
// its 128x128-float output tile (8 coalesced STG.128/thread).

#define E_DIM 512
#define K_ROWS 64
#define THREADS 512
#define COLS4 (E_DIM / 4)       // 128 float4 per full row
#define CB4 32                  // float4 columns per col-block (4 blocks)
#define ROWS_PER_CTA 128        // 32 row-blocks cover 4096 rows
#define GROUPS 16               // 512 threads / 32 columns

__global__ void __launch_bounds__(THREADS)
fused_mean_broadcast(const float4* __restrict__ knowledge4,
                     float4* __restrict__ out, int rows) {
    __shared__ float4 part[GROUPS * CB4];   // 16 partials x 32 cols, 8KB

    int t = threadIdx.x;
    int c = t & (CB4 - 1);      // column within block: 0..31
    int g = t >> 5;             // group 0..15: sums rows [4g, 4g+4)

    int cb = blockIdx.x & 3;          // column block 0..3
    int rb = blockIdx.x >> 2;         // row block 0..31
    int col = cb * CB4 + c;           // global float4 column

    // 4 independent loads per thread (coalesced: warp spans 32 consec float4).
    float4 s = make_float4(0.f, 0.f, 0.f, 0.f);
#pragma unroll
    for (int k = 0; k < 4; ++k) {
        float4 a = knowledge4[(g * 4 + k) * COLS4 + col];
        s.x += a.x; s.y += a.y; s.z += a.z; s.w += a.w;
    }
    part[g * CB4 + c] = s;
    __syncthreads();

    // Tree-reduce 16 partials -> part[c].
#pragma unroll
    for (int step = GROUPS / 2; step >= 1; step >>= 1) {
        if (g < step) {
            float4 a = part[g * CB4 + c];
            float4 b = part[(g + step) * CB4 + c];
            a.x += b.x; a.y += b.y; a.z += b.z; a.w += b.w;
            part[g * CB4 + c] = a;
        }
        __syncthreads();
    }

    const float inv = 1.0f / (float)K_ROWS;
    float4 m = part[c];          // broadcast read, conflict-free
    m.x *= inv; m.y *= inv; m.z *= inv; m.w *= inv;

    // CTA writes rows [rb*128, rb*128+128) of its column block.
    // Group g writes 8 rows; warp stores 32 consecutive float4 (coalesced).
    int r0 = rb * ROWS_PER_CTA + g * (ROWS_PER_CTA / GROUPS);
    size_t base = (size_t)r0 * COLS4 + col;
#pragma unroll
    for (int r = 0; r < ROWS_PER_CTA / GROUPS; ++r) {
        if (r0 + r < rows)
            out[base + (size_t)r * COLS4] = m;
    }
}

extern "C" void kernel_launch(void* const* d_in, const int* in_sizes, int n_in,
                              void* d_out, int out_size) {
    // d_in[0]: query_embedding [4,1024,512] f32 (unused — output is query-independent)
    // d_in[1]: knowledge [64,512] f32
    const float* knowledge = (const float*)d_in[1];
    float* out = (float*)d_out;

    int rows = out_size / E_DIM;                            // 4096
    int blocks = 4 * ((rows + ROWS_PER_CTA - 1) / ROWS_PER_CTA); // 128

    fused_mean_broadcast<<<blocks, THREADS>>>(
        reinterpret_cast<const float4*>(knowledge),
        reinterpret_cast<float4*>(out), rows);
}

// round 9
// speedup vs baseline: 1.0048x; 1.0048x over previous
#include <cuda_runtime.h>
#include <cuda_bf16.h>

// Output[b,s,:] == mean(knowledge, axis=0) for every (b,s):
// top_k with max_chunks == K selects a permutation of ALL knowledge rows,
// so mean(take(knowledge, top_k), axis=1) == mean(knowledge, axis=0).
//
// R8 lesson: profiled time tracks the exposed cold-load phase; barriers are
// cheap. Total = profiled + ~1.3us replay overhead. This round: finer
// tiling. 256 CTAs = 8 col-blocks x 32 row-blocks (2 CTAs/SM, one wave).
// Per CTA: 16-float4-wide column slice, 2 loads/thread, 5-step smem tree
// reduce (32 partials), 4 coalesced STG.128/thread store tail.

#define E_DIM 512
#define K_ROWS 64
#define THREADS 512
#define COLS4 (E_DIM / 4)       // 128 float4 per full row
#define NCB 8                   // column blocks
#define CB4 (COLS4 / NCB)       // 16 float4 columns per block
#define ROWS_PER_CTA 128        // 32 row-blocks cover 4096 rows
#define GROUPS 32               // 512 threads / 16 columns

__global__ void __launch_bounds__(THREADS)
fused_mean_broadcast(const float4* __restrict__ knowledge4,
                     float4* __restrict__ out, int rows) {
    __shared__ float4 part[GROUPS * CB4];   // 32 partials x 16 cols, 8KB

    int t = threadIdx.x;
    int c = t & (CB4 - 1);      // column within block: 0..15
    int g = t >> 4;             // group 0..31: sums rows [2g, 2g+2)

    int cb = blockIdx.x & (NCB - 1);   // column block 0..7
    int rb = blockIdx.x >> 3;          // row block 0..31
    int col = cb * CB4 + c;            // global float4 column

    // 2 independent loads per thread, front-batched.
    float4 a0 = knowledge4[(g * 2 + 0) * COLS4 + col];
    float4 a1 = knowledge4[(g * 2 + 1) * COLS4 + col];
    float4 s;
    s.x = a0.x + a1.x; s.y = a0.y + a1.y;
    s.z = a0.z + a1.z; s.w = a0.w + a1.w;
    part[g * CB4 + c] = s;
    __syncthreads();

    // Tree-reduce 32 partials -> part[c]. 5 barrier steps (~cheap).
#pragma unroll
    for (int step = GROUPS / 2; step >= 1; step >>= 1) {
        if (g < step) {
            float4 a = part[g * CB4 + c];
            float4 b = part[(g + step) * CB4 + c];
            a.x += b.x; a.y += b.y; a.z += b.z; a.w += b.w;
            part[g * CB4 + c] = a;
        }
        __syncthreads();
    }

    const float inv = 1.0f / (float)K_ROWS;
    float4 m = part[c];          // broadcast read, conflict-free
    m.x *= inv; m.y *= inv; m.z *= inv; m.w *= inv;

    // CTA writes rows [rb*128, rb*128+128) of its 16-float4 column slice.
    // Group g writes 4 rows; each warp store = 2 x 256B segments (coalesced).
    int r0 = rb * ROWS_PER_CTA + g * (ROWS_PER_CTA / GROUPS);
    size_t base = (size_t)r0 * COLS4 + col;
#pragma unroll
    for (int r = 0; r < ROWS_PER_CTA / GROUPS; ++r) {
        if (r0 + r < rows)
            out[base + (size_t)r * COLS4] = m;
    }
}

extern "C" void kernel_launch(void* const* d_in, const int* in_sizes, int n_in,
                              void* d_out, int out_size) {
    // d_in[0]: query_embedding [4,1024,512] f32 (unused — output is query-independent)
    // d_in[1]: knowledge [64,512] f32
    const float* knowledge = (const float*)d_in[1];
    float* out = (float*)d_out;

    int rows = out_size / E_DIM;                                 // 4096
    int blocks = NCB * ((rows + ROWS_PER_CTA - 1) / ROWS_PER_CTA); // 256

    fused_mean_broadcast<<<blocks, THREADS>>>(
        reinterpret_cast<const float4*>(knowledge),
        reinterpret_cast<float4*>(out), rows);
}